// round 16
// baseline (speedup 1.0000x reference)
#include <cuda_runtime.h>
#include <cstdint>

#define B_ 2
#define L_ 384
#define H_ 256
#define A_ 14
#define BL (B_ * L_)      // 768
#define IT 4              // i's per block
#define NIG (BL / IT)     // 192 i-groups
#define NJT 3             // j-tiles of 128
#define JTL 128
#define H2 (H_ / 2)       // 128 packed half2 per row

// ---------------- scratch (static device globals; no allocations) ----------------
__device__ __align__(16) uint32_t g_hwh[BL * H2];   // packed f16x2
__device__ __align__(16) uint32_t g_huh[BL * H2];
__device__ float g_S[BL * A_ * 4];  // [bi][a][q]

// ---------------- helpers ----------------
__device__ __forceinline__ void cp16(uint32_t s, const void* g) {
    asm volatile("cp.async.cg.shared.global [%0], [%1], 16;" :: "r"(s), "l"(g));
}
__device__ __forceinline__ void cp_commit() { asm volatile("cp.async.commit_group;"); }
template<int N> __device__ __forceinline__ void cp_wait() {
    asm volatile("cp.async.wait_group %0;" :: "n"(N));
}
__device__ __forceinline__ uint32_t smem_u32(const void* p) {
    uint32_t a;
    asm("{ .reg .u64 t; cvta.to.shared.u64 t, %1; cvt.u32.u64 %0, t; }" : "=r"(a) : "l"(p));
    return a;
}
__device__ __forceinline__ uint32_t tf32r(float x) {
    uint32_t r;
    asm("cvt.rna.tf32.f32 %0, %1;" : "=r"(r) : "f"(x));
    return r;
}
__device__ __forceinline__ uint32_t f2h2(float lo, float hi) {
    uint32_t r;
    asm("cvt.rn.f16x2.f32 %0, %1, %2;" : "=r"(r) : "f"(hi), "f"(lo));
    return r;
}
__device__ __forceinline__ uint32_t hadd2max0(uint32_t a, uint32_t b) {
    uint32_t r;
    asm("{ .reg .b32 s; add.f16x2 s, %1, %2; max.f16x2 %0, s, %3; }"
        : "=r"(r) : "r"(a), "r"(b), "r"(0u));
    return r;
}
__device__ __forceinline__ void mma_tf32(float* d, uint32_t a0, uint32_t a1,
                                         uint32_t a2, uint32_t a3,
                                         uint32_t b0, uint32_t b1) {
    asm volatile(
        "mma.sync.aligned.m16n8k8.row.col.f32.tf32.tf32.f32 "
        "{%0,%1,%2,%3}, {%4,%5,%6,%7}, {%8,%9}, {%0,%1,%2,%3};"
        : "+f"(d[0]), "+f"(d[1]), "+f"(d[2]), "+f"(d[3])
        : "r"(a0), "r"(a1), "r"(a2), "r"(a3), "r"(b0), "r"(b1));
}
__device__ __forceinline__ void mma_f16(float* d, uint32_t a0, uint32_t a1,
                                        uint32_t a2, uint32_t a3,
                                        uint32_t b0, uint32_t b1) {
    asm volatile(
        "mma.sync.aligned.m16n8k16.row.col.f32.f16.f16.f32 "
        "{%0,%1,%2,%3}, {%4,%5,%6,%7}, {%8,%9}, {%0,%1,%2,%3};"
        : "+f"(d[0]), "+f"(d[1]), "+f"(d[2]), "+f"(d[3])
        : "r"(a0), "r"(a1), "r"(a2), "r"(a3), "r"(b0), "r"(b1));
}

// ---------------- kernel 1: hw/hu = h@W^T+b via tf32 mma.sync ----------------
// Block = 64x32 C-tile, 128 threads (4 warps; warp = m16 x n32).
// K in 8 chunks of 32, cp.async double-buffered. Output packed f16x2.
#define GP 36   // smem float pitch ((4g+c)%32 -> conflict-free fragment LDS)
__global__ __launch_bounds__(128) void gemm_k(
    const float* __restrict__ h,
    const float* __restrict__ Wx, const float* __restrict__ Wxb,
    const float* __restrict__ Ux, const float* __restrict__ Uxb)
{
    {   // zero partial-sum accumulator (43008 floats over 24576 threads)
        int fb = blockIdx.x + 12 * (blockIdx.y + 8 * blockIdx.z);
        for (int gtid = fb * 128 + threadIdx.x; gtid < BL * A_ * 4; gtid += 192 * 128)
            g_S[gtid] = 0.f;
    }
    const int z = blockIdx.z;
    const float* W    = z ? Ux  : Wx;
    const float* bias = z ? Uxb : Wxb;
    const int m0 = blockIdx.x * 64;
    const int n0 = blockIdx.y * 32;

    __shared__ float As[2][64 * GP];   // [buf][m][k(32)]
    __shared__ float Bs[2][32 * GP];   // [buf][n][k(32)]

    const int t = threadIdx.x, w = t >> 5, lane = t & 31;
    const int g = lane >> 2, c = lane & 3;
    const uint32_t as0 = smem_u32(As), bs0 = smem_u32(Bs);

    float acc[4][4];   // [ntile][reg]
    #pragma unroll
    for (int nt = 0; nt < 4; nt++)
        #pragma unroll
        for (int r = 0; r < 4; r++) acc[nt][r] = 0.f;

    // stage chunk 0
    {
        #pragma unroll
        for (int q = 0; q < 4; q++) {           // A: 64 rows x 8 cp16
            int idx = t + q * 128, r = idx >> 3, c4 = idx & 7;
            cp16(as0 + (uint32_t)(r * GP + c4 * 4) * 4, h + (m0 + r) * H_ + c4 * 4);
        }
        #pragma unroll
        for (int q = 0; q < 2; q++) {           // B: 32 rows x 8 cp16
            int idx = t + q * 128, r = idx >> 3, c4 = idx & 7;
            cp16(bs0 + (uint32_t)(r * GP + c4 * 4) * 4, W + (n0 + r) * H_ + c4 * 4);
        }
        cp_commit();
    }

    for (int kc = 0; kc < 8; kc++) {
        if (kc < 7) {   // stage next chunk into other buffer
            uint32_t ad = as0 + (uint32_t)(((kc + 1) & 1) * 64 * GP) * 4;
            uint32_t bd = bs0 + (uint32_t)(((kc + 1) & 1) * 32 * GP) * 4;
            const float* hs = h + (kc + 1) * 32;
            const float* ws = W + (kc + 1) * 32;
            #pragma unroll
            for (int q = 0; q < 4; q++) {
                int idx = t + q * 128, r = idx >> 3, c4 = idx & 7;
                cp16(ad + (uint32_t)(r * GP + c4 * 4) * 4, hs + (m0 + r) * H_ + c4 * 4);
            }
            #pragma unroll
            for (int q = 0; q < 2; q++) {
                int idx = t + q * 128, r = idx >> 3, c4 = idx & 7;
                cp16(bd + (uint32_t)(r * GP + c4 * 4) * 4, ws + (n0 + r) * H_ + c4 * 4);
            }
            cp_commit();
            cp_wait<1>();
        } else {
            cp_wait<0>();
        }
        __syncthreads();   // chunk kc staged; prior iter's reads of the other buf done

        const float* A = As[kc & 1];
        const float* Bb = Bs[kc & 1];
        #pragma unroll
        for (int k8 = 0; k8 < 4; k8++) {
            const int kk = k8 * 8;
            uint32_t a0 = tf32r(A[(16 * w + g) * GP + kk + c]);
            uint32_t a1 = tf32r(A[(16 * w + g + 8) * GP + kk + c]);
            uint32_t a2 = tf32r(A[(16 * w + g) * GP + kk + c + 4]);
            uint32_t a3 = tf32r(A[(16 * w + g + 8) * GP + kk + c + 4]);
            #pragma unroll
            for (int nt = 0; nt < 4; nt++) {
                uint32_t b0 = tf32r(Bb[(nt * 8 + g) * GP + kk + c]);
                uint32_t b1 = tf32r(Bb[(nt * 8 + g) * GP + kk + c + 4]);
                mma_tf32(acc[nt], a0, a1, a2, a3, b0, b1);
            }
        }
        __syncthreads();   // reads done before restage
    }

    // epilogue: d0,d1 are n-adjacent -> pack f16x2 directly
    uint32_t* dst = z ? g_huh : g_hwh;
    #pragma unroll
    for (int nt = 0; nt < 4; nt++) {
        int n = n0 + nt * 8 + 2 * c;
        float b0 = bias[n], b1 = bias[n + 1];
        int col = (n >> 1);
        dst[(m0 + 16 * w + g) * H2 + col]     = f2h2(acc[nt][0] + b0, acc[nt][1] + b1);
        dst[(m0 + 16 * w + g + 8) * H2 + col] = f2h2(acc[nt][2] + b0, acc[nt][3] + b1);
    }
}

// ---------------- kernel 2: f16 mma.sync pairwise gate + partial fold ----------------
// (exact 49.0us configuration)
#define TX2_U  (16 * 132)
#define HW2_U  (IT * H2)
#define HUP2   20
#define HUBUF2 (JTL * HUP2)
#define SMEM_U (TX2_U + HW2_U + 2 * HUBUF2)   // 7744 u32 = 30976 B
#define SMEM_BYTES (SMEM_U * 4)

__global__ __launch_bounds__(256) void pair_k(
    const float* __restrict__ X, const int* __restrict__ mask,
    const float* __restrict__ Txw, const float* __restrict__ Txb)
{
    extern __shared__ float smf[];
    uint32_t* tx2 = (uint32_t*)smf;            // [16][132] f16x2 Tx (rows 14,15 zero)
    uint32_t* hw2 = tx2 + TX2_U;               // [4][128]
    uint32_t* hub = hw2 + HW2_U;               // 2 x [128][20]
    float*    xm  = smf;                       // overlay after MMA: [128][14][4]
    __shared__ float txbs[16];

    const int t = threadIdx.x, w = t >> 5, lane = t & 31;
    const int g = lane >> 2, c = lane & 3;
    const int ig = blockIdx.x, jt = blockIdx.y;
    const int ibase = ig * IT;
    const int b  = ibase / L_;
    const int j0 = jt * JTL;

    const uint32_t hub0 = smem_u32(hub);
    const uint32_t* hus = g_huh + (size_t)(b * L_ + j0) * H2;

    {
        #pragma unroll
        for (int q = 0; q < 2; q++) {
            int idx = t + q * 256, r = idx >> 2, c4 = idx & 3;
            cp16(hub0 + (uint32_t)(r * HUP2 + c4 * 4) * 4, hus + r * H2 + c4 * 4);
        }
        cp_commit();
    }
    for (int idx = t; idx < 16 * H2; idx += 256) {
        int a = idx >> 7, h2 = idx & 127;
        uint32_t v = 0u;
        if (a < A_) v = f2h2(Txw[a * H_ + 2 * h2], Txw[a * H_ + 2 * h2 + 1]);
        tx2[a * 132 + h2] = v;
    }
    if (t < 16) txbs[t] = (t < A_) ? Txb[t] : 0.f;
    for (int idx = t; idx < IT * H2; idx += 256)
        hw2[idx] = g_hwh[ibase * H2 + idx];

    float acc[IT][2][4];
    #pragma unroll
    for (int i = 0; i < IT; i++)
        #pragma unroll
        for (int n = 0; n < 2; n++)
            #pragma unroll
            for (int r = 0; r < 4; r++) acc[i][n][r] = 0.f;

    const int jr0 = w * 16 + g, jr1 = jr0 + 8;

    for (int kc = 0; kc < 8; kc++) {
        if (kc < 7) {
            uint32_t dst = hub0 + (uint32_t)(((kc + 1) & 1) * HUBUF2) * 4;
            const uint32_t* src = hus + (kc + 1) * 16;
            #pragma unroll
            for (int q = 0; q < 2; q++) {
                int idx = t + q * 256, r = idx >> 2, c4 = idx & 3;
                cp16(dst + (uint32_t)(r * HUP2 + c4 * 4) * 4, src + r * H2 + c4 * 4);
            }
            cp_commit();
            cp_wait<1>();
        } else {
            cp_wait<0>();
        }
        __syncthreads();

        const uint32_t* hb = hub + (kc & 1) * HUBUF2;
        #pragma unroll
        for (int ks = 0; ks < 2; ks++) {
            const int h2b = kc * 16 + ks * 8;
            const int kl2 = ks * 8;
            uint32_t b00 = tx2[g * 132 + h2b + c];
            uint32_t b01 = tx2[g * 132 + h2b + c + 4];
            uint32_t b10 = tx2[(g + 8) * 132 + h2b + c];
            uint32_t b11 = tx2[(g + 8) * 132 + h2b + c + 4];
            uint32_t h0c  = hb[jr0 * HUP2 + kl2 + c];
            uint32_t h1c  = hb[jr1 * HUP2 + kl2 + c];
            uint32_t h0c4 = hb[jr0 * HUP2 + kl2 + c + 4];
            uint32_t h1c4 = hb[jr1 * HUP2 + kl2 + c + 4];
            #pragma unroll
            for (int i = 0; i < IT; i++) {
                uint32_t wc  = hw2[i * H2 + h2b + c];
                uint32_t wc4 = hw2[i * H2 + h2b + c + 4];
                uint32_t a0 = hadd2max0(h0c,  wc);
                uint32_t a1 = hadd2max0(h1c,  wc);
                uint32_t a2 = hadd2max0(h0c4, wc4);
                uint32_t a3 = hadd2max0(h1c4, wc4);
                mma_f16(acc[i][0], a0, a1, a2, a3, b00, b01);
                mma_f16(acc[i][1], a0, a1, a2, a3, b10, b11);
            }
        }
        __syncthreads();
    }

    for (int idx = t; idx < JTL * A_; idx += 256) {
        int j = idx / A_, a = idx % A_;
        float m = (float)mask[b * L_ + j0 + j];
        const float* xp = X + ((size_t)(b * L_ + j0 + j) * A_ + a) * 3;
        float* d = xm + idx * 4;
        d[0] = xp[0] * m; d[1] = xp[1] * m; d[2] = xp[2] * m; d[3] = m;
    }
    __syncthreads();

    const float tb[4] = { txbs[2 * c], txbs[2 * c + 1], txbs[8 + 2 * c], txbs[9 + 2 * c] };
    #pragma unroll
    for (int i = 0; i < IT; i++) {
        float f[4][4];
        #pragma unroll
        for (int s = 0; s < 4; s++)
            #pragma unroll
            for (int q = 0; q < 4; q++) f[s][q] = 0.f;

        #pragma unroll
        for (int n = 0; n < 2; n++) {
            int an = n * 8 + 2 * c;
            #pragma unroll
            for (int r = 0; r < 4; r++) {
                int jr = (r >> 1) ? jr1 : jr0;
                int a  = an + (r & 1);
                int s  = n * 2 + (r & 1);
                float v = acc[i][n][r] + tb[s];
                const float* xp = xm + (jr * A_ + a) * 4;
                float4 x4 = *(const float4*)xp;
                f[s][0] += v * x4.x; f[s][1] += v * x4.y;
                f[s][2] += v * x4.z; f[s][3] += v * x4.w;
            }
        }
        #pragma unroll
        for (int s = 0; s < 4; s++)
            #pragma unroll
            for (int q = 0; q < 4; q++) {
                float v = f[s][q];
                v += __shfl_xor_sync(0xffffffffu, v, 4);
                v += __shfl_xor_sync(0xffffffffu, v, 8);
                v += __shfl_xor_sync(0xffffffffu, v, 16);
                f[s][q] = v;
            }
        if (lane < 4) {
            #pragma unroll
            for (int s = 0; s < 4; s++) {
                int a = (s >> 1) * 8 + 2 * lane + (s & 1);
                if (a < A_) {
                    #pragma unroll
                    for (int q = 0; q < 4; q++)
                        atomicAdd(&g_S[((ibase + i) * A_ + a) * 4 + q], f[s][q]);
                }
            }
        }
    }
}

// ---------------- kernel 3: finalize ----------------
__global__ void fin_k(const float* __restrict__ X, const int* __restrict__ mask,
                      float* __restrict__ out)
{
    const int bi = blockIdx.x, t = threadIdx.x;
    const int b = bi / L_;
    __shared__ float smv[64];
    float s = 0.f;
    for (int j = t; j < L_; j += 64) s += (float)mask[b * L_ + j];
    smv[t] = s;
    __syncthreads();
    if (t == 0) {
        float tot = 0.f;
        for (int k = 0; k < 64; k++) tot += smv[k];
        smv[0] = tot;
    }
    __syncthreads();
    if (t < A_ * 3) {
        int a = t / 3, c = t % 3;
        float S = g_S[(bi * A_ + a) * 4 + c];
        float G = g_S[(bi * A_ + a) * 4 + 3];
        float Xi = X[((size_t)bi * A_ + a) * 3 + c];
        float f = (Xi * G - S) / (1e-6f + smv[0]);
        f = fminf(fmaxf(f, -20.f), 20.f);
        out[((size_t)bi * A_ + a) * 3 + c] = Xi + f;
    }
}

// ---------------- launch ----------------
extern "C" void kernel_launch(void* const* d_in, const int* in_sizes, int n_in,
                              void* d_out, int out_size) {
    const float* h    = (const float*)d_in[0];
    const float* X    = (const float*)d_in[1];
    const int*   mask = (const int*)  d_in[2];
    const float* Wxw  = (const float*)d_in[3];
    const float* Wxb  = (const float*)d_in[4];
    const float* Uxw  = (const float*)d_in[5];
    const float* Uxb  = (const float*)d_in[6];
    const float* Txw  = (const float*)d_in[7];
    const float* Txb  = (const float*)d_in[8];
    float* out = (float*)d_out;

    cudaFuncSetAttribute(pair_k, cudaFuncAttributeMaxDynamicSharedMemorySize, SMEM_BYTES);

    gemm_k<<<dim3(12, 8, 2), 128>>>(h, Wxw, Wxb, Uxw, Uxb);
    pair_k<<<dim3(NIG, NJT), 256, SMEM_BYTES>>>(X, mask, Txw, Txb);
    fin_k<<<BL, 64>>>(X, mask, out);
}

// round 17
// speedup vs baseline: 1.2760x; 1.2760x over previous
#include <cuda_runtime.h>
#include <cstdint>

#define B_ 2
#define L_ 384
#define H_ 256
#define A_ 14
#define BL (B_ * L_)      // 768
#define IT 4              // i's per block
#define NIG (BL / IT)     // 192 i-groups
#define NJT 3             // j-tiles of 128
#define JTL 128
#define H2 (H_ / 2)       // 128 packed half2 per row

// ---------------- scratch (static device globals; no allocations) ----------------
__device__ __align__(16) uint32_t g_hwh[BL * H2];   // packed f16x2
__device__ __align__(16) uint32_t g_huh[BL * H2];
__device__ float g_S[BL * A_ * 4];  // [bi][a][q]

// ---------------- helpers ----------------
__device__ __forceinline__ void cp16(uint32_t s, const void* g) {
    asm volatile("cp.async.cg.shared.global [%0], [%1], 16;" :: "r"(s), "l"(g));
}
__device__ __forceinline__ void cp_commit() { asm volatile("cp.async.commit_group;"); }
template<int N> __device__ __forceinline__ void cp_wait() {
    asm volatile("cp.async.wait_group %0;" :: "n"(N));
}
__device__ __forceinline__ uint32_t smem_u32(const void* p) {
    uint32_t a;
    asm("{ .reg .u64 t; cvta.to.shared.u64 t, %1; cvt.u32.u64 %0, t; }" : "=r"(a) : "l"(p));
    return a;
}
__device__ __forceinline__ uint32_t tf32r(float x) {
    uint32_t r;
    asm("cvt.rna.tf32.f32 %0, %1;" : "=r"(r) : "f"(x));
    return r;
}
__device__ __forceinline__ uint32_t f2h2(float lo, float hi) {
    uint32_t r;
    asm("cvt.rn.f16x2.f32 %0, %1, %2;" : "=r"(r) : "f"(hi), "f"(lo));
    return r;
}
__device__ __forceinline__ uint32_t hadd2max0(uint32_t a, uint32_t b) {
    uint32_t r;
    asm("{ .reg .b32 s; add.f16x2 s, %1, %2; max.f16x2 %0, s, %3; }"
        : "=r"(r) : "r"(a), "r"(b), "r"(0u));
    return r;
}
__device__ __forceinline__ void mma_tf32(float* d, uint32_t a0, uint32_t a1,
                                         uint32_t a2, uint32_t a3,
                                         uint32_t b0, uint32_t b1) {
    asm volatile(
        "mma.sync.aligned.m16n8k8.row.col.f32.tf32.tf32.f32 "
        "{%0,%1,%2,%3}, {%4,%5,%6,%7}, {%8,%9}, {%0,%1,%2,%3};"
        : "+f"(d[0]), "+f"(d[1]), "+f"(d[2]), "+f"(d[3])
        : "r"(a0), "r"(a1), "r"(a2), "r"(a3), "r"(b0), "r"(b1));
}
__device__ __forceinline__ void mma_f16(float* d, uint32_t a0, uint32_t a1,
                                        uint32_t a2, uint32_t a3,
                                        uint32_t b0, uint32_t b1) {
    asm volatile(
        "mma.sync.aligned.m16n8k16.row.col.f32.f16.f16.f32 "
        "{%0,%1,%2,%3}, {%4,%5,%6,%7}, {%8,%9}, {%0,%1,%2,%3};"
        : "+f"(d[0]), "+f"(d[1]), "+f"(d[2]), "+f"(d[3])
        : "r"(a0), "r"(a1), "r"(a2), "r"(a3), "r"(b0), "r"(b1));
}

// ---------------- kernel 1: hw/hu = h@W^T+b via tf32 mma.sync ----------------
// Block = 64x32 C-tile, 256 threads (8 warps: warp = m16 x n16).
// K in 8 chunks of 32, 3-stage cp.async pipeline, ONE sync per chunk.
#define GP 36   // smem float pitch ((4g+c)%32 -> conflict-free fragment LDS)
__global__ __launch_bounds__(256) void gemm_k(
    const float* __restrict__ h,
    const float* __restrict__ Wx, const float* __restrict__ Wxb,
    const float* __restrict__ Ux, const float* __restrict__ Uxb)
{
    {   // zero partial-sum accumulator
        int fb = blockIdx.x + 12 * (blockIdx.y + 8 * blockIdx.z);
        for (int gtid = fb * 256 + threadIdx.x; gtid < BL * A_ * 4; gtid += 192 * 256)
            g_S[gtid] = 0.f;
    }
    const int z = blockIdx.z;
    const float* W    = z ? Ux  : Wx;
    const float* bias = z ? Uxb : Wxb;
    const int m0 = blockIdx.x * 64;
    const int n0 = blockIdx.y * 32;

    __shared__ float As[3][64 * GP];   // [buf][m][k(32)]
    __shared__ float Bs[3][32 * GP];   // [buf][n][k(32)]

    const int t = threadIdx.x, w = t >> 5, lane = t & 31;
    const int g = lane >> 2, c = lane & 3;
    const int mw = w & 3, nw = w >> 2;          // warp = m16(mw) x n16(nw)
    const uint32_t as0 = smem_u32(As), bs0 = smem_u32(Bs);

    float acc[2][4];   // [ntile][reg]
    #pragma unroll
    for (int nt = 0; nt < 2; nt++)
        #pragma unroll
        for (int r = 0; r < 4; r++) acc[nt][r] = 0.f;

    // staging lambda-ish (manual): chunk cc -> buf bi
    const int sr_a = t >> 3, sc_a = t & 7;      // A: 2 cp16/thread
    #define G_STAGE(cc, bi)                                                        \
    {                                                                              \
        uint32_t ad = as0 + (uint32_t)((bi) * 64 * GP) * 4;                        \
        uint32_t bd = bs0 + (uint32_t)((bi) * 32 * GP) * 4;                        \
        const float* hs = h + (cc) * 32;                                           \
        const float* ws = W + (cc) * 32;                                           \
        cp16(ad + (uint32_t)(sr_a * GP + sc_a * 4) * 4,                            \
             hs + (m0 + sr_a) * H_ + sc_a * 4);                                    \
        cp16(ad + (uint32_t)((sr_a + 32) * GP + sc_a * 4) * 4,                     \
             hs + (m0 + sr_a + 32) * H_ + sc_a * 4);                               \
        if (t < 256) { /* B: 1 cp16/thread */                                      \
            cp16(bd + (uint32_t)(sr_a * GP + sc_a * 4) * 4,                        \
                 ws + (n0 + (sr_a & 31)) * H_ + sc_a * 4);                         \
        }                                                                          \
        cp_commit();                                                               \
    }
    // NOTE: B staging uses rows 0..31 twice is wrong; do B with half the threads:
    #undef G_STAGE

    // prologue: stage chunks 0,1
    #pragma unroll
    for (int p = 0; p < 2; p++) {
        uint32_t ad = as0 + (uint32_t)(p * 64 * GP) * 4;
        uint32_t bd = bs0 + (uint32_t)(p * 32 * GP) * 4;
        const float* hs = h + p * 32;
        const float* ws = W + p * 32;
        cp16(ad + (uint32_t)(sr_a * GP + sc_a * 4) * 4, hs + (m0 + sr_a) * H_ + sc_a * 4);
        cp16(ad + (uint32_t)((sr_a + 32) * GP + sc_a * 4) * 4,
             hs + (m0 + sr_a + 32) * H_ + sc_a * 4);
        if (t < 256 && sr_a < 32)
            cp16(bd + (uint32_t)(sr_a * GP + sc_a * 4) * 4, ws + (n0 + sr_a) * H_ + sc_a * 4);
        else if (sr_a >= 32)
            ; // threads 256..: none (blockDim=256, sr_a<=31 for t<256? sr_a = t>>3 up to 31) 
        cp_commit();
    }
    // (sr_a ranges 0..31 for t<256, so ALL threads also stage one B row-segment:
    //  rows 0..31 x 8 segs = 256 = blockDim — covered exactly once above.)

    for (int kc = 0; kc < 8; kc++) {
        if (kc == 7) cp_wait<0>(); else cp_wait<1>();
        __syncthreads();

        const float* A  = As[kc % 3];
        const float* Bb = Bs[kc % 3];
        #pragma unroll
        for (int k8 = 0; k8 < 4; k8++) {
            const int kk = k8 * 8;
            uint32_t a0 = tf32r(A[(16 * mw + g) * GP + kk + c]);
            uint32_t a1 = tf32r(A[(16 * mw + g + 8) * GP + kk + c]);
            uint32_t a2 = tf32r(A[(16 * mw + g) * GP + kk + c + 4]);
            uint32_t a3 = tf32r(A[(16 * mw + g + 8) * GP + kk + c + 4]);
            #pragma unroll
            for (int nt = 0; nt < 2; nt++) {
                uint32_t b0 = tf32r(Bb[(nw * 16 + nt * 8 + g) * GP + kk + c]);
                uint32_t b1 = tf32r(Bb[(nw * 16 + nt * 8 + g) * GP + kk + c + 4]);
                mma_tf32(acc[nt], a0, a1, a2, a3, b0, b1);
            }
        }

        if (kc + 2 < 8) {
            const int cc = kc + 2, bi = cc % 3;
            uint32_t ad = as0 + (uint32_t)(bi * 64 * GP) * 4;
            uint32_t bd = bs0 + (uint32_t)(bi * 32 * GP) * 4;
            const float* hs = h + cc * 32;
            const float* ws = W + cc * 32;
            cp16(ad + (uint32_t)(sr_a * GP + sc_a * 4) * 4, hs + (m0 + sr_a) * H_ + sc_a * 4);
            cp16(ad + (uint32_t)((sr_a + 32) * GP + sc_a * 4) * 4,
                 hs + (m0 + sr_a + 32) * H_ + sc_a * 4);
            cp16(bd + (uint32_t)(sr_a * GP + sc_a * 4) * 4, ws + (n0 + sr_a) * H_ + sc_a * 4);
            cp_commit();
        }
    }

    // epilogue: d0,d1 n-adjacent -> pack f16x2
    uint32_t* dst = z ? g_huh : g_hwh;
    #pragma unroll
    for (int nt = 0; nt < 2; nt++) {
        int n = n0 + nw * 16 + nt * 8 + 2 * c;
        float b0 = bias[n], b1 = bias[n + 1];
        int col = (n >> 1);
        dst[(m0 + 16 * mw + g) * H2 + col]     = f2h2(acc[nt][0] + b0, acc[nt][1] + b1);
        dst[(m0 + 16 * mw + g + 8) * H2 + col] = f2h2(acc[nt][2] + b0, acc[nt][3] + b1);
    }
}

// ---------------- kernel 2: f16 mma.sync pairwise gate + partial fold ----------------
// 3-stage hu pipeline, ONE sync per chunk; epilogue block-reduced atomics.
#define TX2_U  (16 * 132)
#define HW2_U  (IT * H2)
#define HUP2   20
#define HUBUF2 (JTL * HUP2)
#define SMEM_U (TX2_U + HW2_U + 3 * HUBUF2)   // 2112+512+7680 = 10304 u32 = 41216 B
#define SMEM_BYTES (SMEM_U * 4)
// overlays after main loop: xm = smf[0 .. 7168) floats (28672B);
//                           red = smf[7168 .. 9216) floats (2048 f = 8KB) -> 36864B < 41216 ✓

__global__ __launch_bounds__(256) void pair_k(
    const float* __restrict__ X, const int* __restrict__ mask,
    const float* __restrict__ Txw, const float* __restrict__ Txb)
{
    extern __shared__ float smf[];
    uint32_t* tx2 = (uint32_t*)smf;            // [16][132] f16x2 Tx (rows 14,15 zero)
    uint32_t* hw2 = tx2 + TX2_U;               // [4][128]
    uint32_t* hub = hw2 + HW2_U;               // 3 x [128][20]
    float*    xm  = smf;                       // overlay: [128][14][4]
    float*    red = smf + 7168;                // overlay: [8 w][256]
    __shared__ float txbs[16];

    const int t = threadIdx.x, w = t >> 5, lane = t & 31;
    const int g = lane >> 2, c = lane & 3;
    const int ig = blockIdx.x, jt = blockIdx.y;
    const int ibase = ig * IT;
    const int b  = ibase / L_;
    const int j0 = jt * JTL;

    const uint32_t hub0 = smem_u32(hub);
    const uint32_t* hus = g_huh + (size_t)(b * L_ + j0) * H2;

    // prologue: stage chunks 0,1 (each: 512 cp16 = 2/thread)
    #pragma unroll
    for (int p = 0; p < 2; p++) {
        uint32_t dstp = hub0 + (uint32_t)(p * HUBUF2) * 4;
        const uint32_t* src = hus + p * 16;
        #pragma unroll
        for (int q = 0; q < 2; q++) {
            int idx = t + q * 256, r = idx >> 2, c4 = idx & 3;
            cp16(dstp + (uint32_t)(r * HUP2 + c4 * 4) * 4, src + r * H2 + c4 * 4);
        }
        cp_commit();
    }
    // stage Tx (f16x2), txb, hw
    for (int idx = t; idx < 16 * H2; idx += 256) {
        int a = idx >> 7, h2 = idx & 127;
        uint32_t v = 0u;
        if (a < A_) v = f2h2(Txw[a * H_ + 2 * h2], Txw[a * H_ + 2 * h2 + 1]);
        tx2[a * 132 + h2] = v;
    }
    if (t < 16) txbs[t] = (t < A_) ? Txb[t] : 0.f;
    for (int idx = t; idx < IT * H2; idx += 256)
        hw2[idx] = g_hwh[ibase * H2 + idx];

    float acc[IT][2][4];
    #pragma unroll
    for (int i = 0; i < IT; i++)
        #pragma unroll
        for (int n = 0; n < 2; n++)
            #pragma unroll
            for (int r = 0; r < 4; r++) acc[i][n][r] = 0.f;

    const int jr0 = w * 16 + g, jr1 = jr0 + 8;

    for (int kc = 0; kc < 8; kc++) {
        if (kc == 7) cp_wait<0>(); else cp_wait<1>();
        __syncthreads();   // chunk kc visible everywhere; buf (kc+2)%3 free

        const uint32_t* hb = hub + (kc % 3) * HUBUF2;
        #pragma unroll
        for (int ks = 0; ks < 2; ks++) {
            const int h2b = kc * 16 + ks * 8;
            const int kl2 = ks * 8;
            uint32_t b00 = tx2[g * 132 + h2b + c];
            uint32_t b01 = tx2[g * 132 + h2b + c + 4];
            uint32_t b10 = tx2[(g + 8) * 132 + h2b + c];
            uint32_t b11 = tx2[(g + 8) * 132 + h2b + c + 4];
            uint32_t h0c  = hb[jr0 * HUP2 + kl2 + c];
            uint32_t h1c  = hb[jr1 * HUP2 + kl2 + c];
            uint32_t h0c4 = hb[jr0 * HUP2 + kl2 + c + 4];
            uint32_t h1c4 = hb[jr1 * HUP2 + kl2 + c + 4];
            #pragma unroll
            for (int i = 0; i < IT; i++) {
                uint32_t wc  = hw2[i * H2 + h2b + c];
                uint32_t wc4 = hw2[i * H2 + h2b + c + 4];
                uint32_t a0 = hadd2max0(h0c,  wc);
                uint32_t a1 = hadd2max0(h1c,  wc);
                uint32_t a2 = hadd2max0(h0c4, wc4);
                uint32_t a3 = hadd2max0(h1c4, wc4);
                mma_f16(acc[i][0], a0, a1, a2, a3, b00, b01);
                mma_f16(acc[i][1], a0, a1, a2, a3, b10, b11);
            }
        }

        if (kc + 2 < 8) {   // stage chunk kc+2 into buf (kc+2)%3
            uint32_t dstp = hub0 + (uint32_t)(((kc + 2) % 3) * HUBUF2) * 4;
            const uint32_t* src = hus + (kc + 2) * 16;
            #pragma unroll
            for (int q = 0; q < 2; q++) {
                int idx = t + q * 256, r = idx >> 2, c4 = idx & 3;
                cp16(dstp + (uint32_t)(r * HUP2 + c4 * 4) * 4, src + r * H2 + c4 * 4);
            }
            cp_commit();
        }
    }
    __syncthreads();   // all compute done before overlays

    // ---- overlay xm = {X*m (q<3), m} ----
    for (int idx = t; idx < JTL * A_; idx += 256) {
        int j = idx / A_, a = idx % A_;
        float m = (float)mask[b * L_ + j0 + j];
        const float* xp = X + ((size_t)(b * L_ + j0 + j) * A_ + a) * 3;
        float* d = xm + idx * 4;
        d[0] = xp[0] * m; d[1] = xp[1] * m; d[2] = xp[2] * m; d[3] = m;
    }
    __syncthreads();

    // ---- fold: per-warp shuffle reduce -> smem red -> block reduce -> atomics ----
    const float tb[4] = { txbs[2 * c], txbs[2 * c + 1], txbs[8 + 2 * c], txbs[9 + 2 * c] };
    #pragma unroll
    for (int i = 0; i < IT; i++) {
        float f[4][4];
        #pragma unroll
        for (int s = 0; s < 4; s++)
            #pragma unroll
            for (int q = 0; q < 4; q++) f[s][q] = 0.f;

        #pragma unroll
        for (int n = 0; n < 2; n++) {
            int an = n * 8 + 2 * c;
            #pragma unroll
            for (int r = 0; r < 4; r++) {
                int jr = (r >> 1) ? jr1 : jr0;
                int a  = an + (r & 1);
                int s  = n * 2 + (r & 1);
                float v = acc[i][n][r] + tb[s];
                const float* xp = xm + (jr * A_ + a) * 4;  // a=14,15 stray (guarded later)
                float4 x4 = *(const float4*)xp;
                f[s][0] += v * x4.x; f[s][1] += v * x4.y;
                f[s][2] += v * x4.z; f[s][3] += v * x4.w;
            }
        }
        #pragma unroll
        for (int s = 0; s < 4; s++)
            #pragma unroll
            for (int q = 0; q < 4; q++) {
                float v = f[s][q];
                v += __shfl_xor_sync(0xffffffffu, v, 4);
                v += __shfl_xor_sync(0xffffffffu, v, 8);
                v += __shfl_xor_sync(0xffffffffu, v, 16);
                f[s][q] = v;
            }
        if (lane < 4) {
            #pragma unroll
            for (int s = 0; s < 4; s++)
                *(float4*)&red[w * 256 + i * 64 + s * 16 + lane * 4] =
                    make_float4(f[s][0], f[s][1], f[s][2], f[s][3]);
        }
    }
    __syncthreads();

    // block reduce over 8 warps: thread t handles combo t = i*64 + s*16 + ln*4 + q
    {
        float sum = 0.f;
        #pragma unroll
        for (int wv = 0; wv < 8; wv++) sum += red[wv * 256 + t];
        int i = t >> 6, s = (t >> 4) & 3, ln = (t >> 2) & 3, q = t & 3;
        int a = (s >> 1) * 8 + 2 * ln + (s & 1);
        if (a < A_)
            atomicAdd(&g_S[((ibase + i) * A_ + a) * 4 + q], sum);
    }
}

// ---------------- kernel 3: finalize ----------------
__global__ void fin_k(const float* __restrict__ X, const int* __restrict__ mask,
                      float* __restrict__ out)
{
    const int bi = blockIdx.x, t = threadIdx.x;
    const int b = bi / L_;
    __shared__ float smv[2];
    float s = 0.f;
    for (int j = t; j < L_; j += 64) s += (float)mask[b * L_ + j];
    #pragma unroll
    for (int o = 16; o; o >>= 1) s += __shfl_xor_sync(0xffffffffu, s, o);
    if ((t & 31) == 0) smv[t >> 5] = s;
    __syncthreads();
    if (t < A_ * 3) {
        int a = t / 3, c = t % 3;
        float denom = 1e-6f + smv[0] + smv[1];
        float S = g_S[(bi * A_ + a) * 4 + c];
        float G = g_S[(bi * A_ + a) * 4 + 3];
        float Xi = X[((size_t)bi * A_ + a) * 3 + c];
        float f = (Xi * G - S) / denom;
        f = fminf(fmaxf(f, -20.f), 20.f);
        out[((size_t)bi * A_ + a) * 3 + c] = Xi + f;
    }
}

// ---------------- launch ----------------
extern "C" void kernel_launch(void* const* d_in, const int* in_sizes, int n_in,
                              void* d_out, int out_size) {
    const float* h    = (const float*)d_in[0];
    const float* X    = (const float*)d_in[1];
    const int*   mask = (const int*)  d_in[2];
    const float* Wxw  = (const float*)d_in[3];
    const float* Wxb  = (const float*)d_in[4];
    const float* Uxw  = (const float*)d_in[5];
    const float* Uxb  = (const float*)d_in[6];
    const float* Txw  = (const float*)d_in[7];
    const float* Txb  = (const float*)d_in[8];
    float* out = (float*)d_out;

    cudaFuncSetAttribute(pair_k, cudaFuncAttributeMaxDynamicSharedMemorySize, SMEM_BYTES);

    gemm_k<<<dim3(12, 8, 2), 256>>>(h, Wxw, Wxb, Uxw, Uxb);
    pair_k<<<dim3(NIG, NJT), 256, SMEM_BYTES>>>(X, mask, Txw, Txb);
    fin_k<<<BL, 64>>>(X, mask, out);
}